// round 2
// baseline (speedup 1.0000x reference)
#include <cuda_runtime.h>

#define BATCH 2048
#define NF 32
#define DIM 64
#define NPAIR 496
#define TILE_B 128

__device__ __forceinline__ unsigned long long dup2(float x) {
    unsigned long long r;
    asm("mov.b64 %0, {%1, %1};" : "=l"(r) : "f"(x));
    return r;
}
__device__ __forceinline__ unsigned long long pack2(float lo, float hi) {
    unsigned long long r;
    asm("mov.b64 %0, {%1, %2};" : "=l"(r) : "f"(lo), "f"(hi));
    return r;
}
__device__ __forceinline__ void ffma2(unsigned long long& acc,
                                      unsigned long long a,
                                      unsigned long long b) {
    asm("fma.rn.f32x2 %0, %1, %2, %0;" : "+l"(acc) : "l"(a), "l"(b));
}

// out[b, p, e] = (sum_d fe[b, i(p), d] * W[p, d, e]) * fe[b, j(p), e]
__global__ __launch_bounds__(128) void bilinear_kernel(
    const float* __restrict__ fe,   // [BATCH, NF, DIM]
    const float* __restrict__ Wg,   // [NPAIR, DIM, DIM]
    float* __restrict__ out)        // [BATCH, NPAIR, DIM]
{
    const int p     = blockIdx.y;       // pair index 0..495
    const int btile = blockIdx.x;       // 0..15 (128 batch rows each)
    const int tid   = threadIdx.x;      // 0..127

    // Decode (i, j) from triu_indices(NF, k=1) row-major order.
    int i = 0, rem = p;
    while (rem >= NF - 1 - i) { rem -= NF - 1 - i; ++i; }
    const int j = i + 1 + rem;

    __shared__ float As[DIM][TILE_B];   // transposed: As[d][row]  (32 KB)
    __shared__ float Ws[DIM][DIM];      // Ws[d][e]                (16 KB)

    // ---- Load A tile: thread t owns batch row (btile*128 + t), 64 floats ----
    {
        const float4* src = reinterpret_cast<const float4*>(
            fe + ((size_t)(btile * TILE_B + tid) * NF + i) * DIM);
        #pragma unroll
        for (int q = 0; q < 16; ++q) {
            float4 v = src[q];
            As[4 * q + 0][tid] = v.x;
            As[4 * q + 1][tid] = v.y;
            As[4 * q + 2][tid] = v.z;
            As[4 * q + 3][tid] = v.w;
        }
    }
    // ---- Load W_p (64x64 contiguous = 1024 float4, 8 per thread) ----
    {
        const float4* src = reinterpret_cast<const float4*>(Wg + (size_t)p * DIM * DIM);
        float4* dst = reinterpret_cast<float4*>(&Ws[0][0]);
        #pragma unroll
        for (int q = 0; q < 8; ++q)
            dst[tid + 128 * q] = src[tid + 128 * q];
    }
    __syncthreads();

    // ---- Compute: each thread owns an 8x8 tile; accumulators are f32x2
    //      pairs over COLUMNS so W pairs come free from ld.shared.v4. ----
    const int tr = (tid >> 3) * 8;   // row base   (16 groups)
    const int tc = (tid & 7)  * 8;   // col base   (8 groups)

    unsigned long long acc[8][4];
    #pragma unroll
    for (int r = 0; r < 8; ++r)
        #pragma unroll
        for (int c = 0; c < 4; ++c)
            acc[r][c] = 0ull;

    #pragma unroll 8
    for (int k = 0; k < DIM; ++k) {
        float4 a0 = *reinterpret_cast<const float4*>(&As[k][tr]);
        float4 a1 = *reinterpret_cast<const float4*>(&As[k][tr + 4]);
        float4 w0 = *reinterpret_cast<const float4*>(&Ws[k][tc]);
        float4 w1 = *reinterpret_cast<const float4*>(&Ws[k][tc + 4]);

        unsigned long long wp0 = pack2(w0.x, w0.y);
        unsigned long long wp1 = pack2(w0.z, w0.w);
        unsigned long long wp2 = pack2(w1.x, w1.y);
        unsigned long long wp3 = pack2(w1.z, w1.w);

        float ar[8] = {a0.x, a0.y, a0.z, a0.w, a1.x, a1.y, a1.z, a1.w};
        #pragma unroll
        for (int r = 0; r < 8; ++r) {
            unsigned long long ad = dup2(ar[r]);
            ffma2(acc[r][0], ad, wp0);
            ffma2(acc[r][1], ad, wp1);
            ffma2(acc[r][2], ad, wp2);
            ffma2(acc[r][3], ad, wp3);
        }
    }

    // ---- Epilogue: scale by v_j and store ----
    const int b0 = btile * TILE_B + tr;
    #pragma unroll
    for (int r = 0; r < 8; ++r) {
        const int b = b0 + r;
        const float* vjp = fe + ((size_t)b * NF + j) * DIM + tc;
        float4 vj0 = *reinterpret_cast<const float4*>(vjp);
        float4 vj1 = *reinterpret_cast<const float4*>(vjp + 4);

        float2 f0 = *reinterpret_cast<float2*>(&acc[r][0]);
        float2 f1 = *reinterpret_cast<float2*>(&acc[r][1]);
        float2 f2 = *reinterpret_cast<float2*>(&acc[r][2]);
        float2 f3 = *reinterpret_cast<float2*>(&acc[r][3]);

        float4 o0 = make_float4(f0.x * vj0.x, f0.y * vj0.y, f1.x * vj0.z, f1.y * vj0.w);
        float4 o1 = make_float4(f2.x * vj1.x, f2.y * vj1.y, f3.x * vj1.z, f3.y * vj1.w);

        float* op = out + ((size_t)b * NPAIR + p) * DIM + tc;
        *reinterpret_cast<float4*>(op)     = o0;
        *reinterpret_cast<float4*>(op + 4) = o1;
    }
}

extern "C" void kernel_launch(void* const* d_in, const int* in_sizes, int n_in,
                              void* d_out, int out_size) {
    const float* fe = (const float*)d_in[0];   // feature_emb [2048, 32, 64] fp32
    const float* W  = (const float*)d_in[1];   // bilinear_W [496, 64, 64] fp32
    float* out = (float*)d_out;                // [2048, 496, 64] fp32

    dim3 grid(BATCH / TILE_B, NPAIR);  // (16, 496)
    bilinear_kernel<<<grid, 128>>>(fe, W, out);
}

// round 4
// speedup vs baseline: 1.7629x; 1.7629x over previous
#include <cuda_runtime.h>
#include <cuda_bf16.h>
#include <cstdint>

#define NF 32
#define DIM 64
#define NPAIR 496
#define BATCH 2048
#define TILE_M 128
#define LDSTR 72                      // bf16 elems per smem row (64 + 8 pad)

// dynamic smem byte offsets
#define SM_WH 0
#define SM_WL (DIM * LDSTR * 2)                    // 9216
#define SM_AH (2 * DIM * LDSTR * 2)                // 18432
#define SM_AL (SM_AH + TILE_M * LDSTR * 2)         // 36864
#define SM_TOTAL (SM_AL + TILE_M * LDSTR * 2)      // 55296

__device__ __forceinline__ uint32_t s2u(const void* p) {
    uint32_t a;
    asm("{ .reg .u64 t; cvta.to.shared.u64 t, %1; cvt.u32.u64 %0, t; }" : "=r"(a) : "l"(p));
    return a;
}
__device__ __forceinline__ void ldsm_x4(uint32_t* r, uint32_t a) {
    asm volatile("ldmatrix.sync.aligned.m8n8.x4.shared.b16 {%0,%1,%2,%3}, [%4];"
                 : "=r"(r[0]), "=r"(r[1]), "=r"(r[2]), "=r"(r[3]) : "r"(a));
}
__device__ __forceinline__ void ldsm_x4t(uint32_t* r, uint32_t a) {
    asm volatile("ldmatrix.sync.aligned.m8n8.x4.trans.shared.b16 {%0,%1,%2,%3}, [%4];"
                 : "=r"(r[0]), "=r"(r[1]), "=r"(r[2]), "=r"(r[3]) : "r"(a));
}
__device__ __forceinline__ void mma_bf16(float* d, const uint32_t* a, const uint32_t* b) {
    asm volatile("mma.sync.aligned.m16n8k16.row.col.f32.bf16.bf16.f32 "
                 "{%0,%1,%2,%3}, {%4,%5,%6,%7}, {%8,%9}, {%0,%1,%2,%3};"
                 : "+f"(d[0]), "+f"(d[1]), "+f"(d[2]), "+f"(d[3])
                 : "r"(a[0]), "r"(a[1]), "r"(a[2]), "r"(a[3]), "r"(b[0]), "r"(b[1]));
}

// split float4 into bf16-hi pair-of-uint32 and bf16-lo pair-of-uint32
__device__ __forceinline__ void split_bf16(float4 v, uint2& h, uint2& l) {
    __nv_bfloat16 hx = __float2bfloat16(v.x);
    __nv_bfloat16 hy = __float2bfloat16(v.y);
    __nv_bfloat16 hz = __float2bfloat16(v.z);
    __nv_bfloat16 hw = __float2bfloat16(v.w);
    __nv_bfloat162 h01 = __halves2bfloat162(hx, hy);
    __nv_bfloat162 h23 = __halves2bfloat162(hz, hw);
    __nv_bfloat162 l01 = __halves2bfloat162(
        __float2bfloat16(v.x - __bfloat162float(hx)),
        __float2bfloat16(v.y - __bfloat162float(hy)));
    __nv_bfloat162 l23 = __halves2bfloat162(
        __float2bfloat16(v.z - __bfloat162float(hz)),
        __float2bfloat16(v.w - __bfloat162float(hw)));
    h.x = *reinterpret_cast<uint32_t*>(&h01);
    h.y = *reinterpret_cast<uint32_t*>(&h23);
    l.x = *reinterpret_cast<uint32_t*>(&l01);
    l.y = *reinterpret_cast<uint32_t*>(&l23);
}

// out[b, p, e] = (sum_d fe[b, i(p), d] * W[p, d, e]) * fe[b, j(p), e]
__global__ __launch_bounds__(256) void bilinear_mma_kernel(
    const float* __restrict__ fe,   // [BATCH, NF, DIM]
    const float* __restrict__ Wg,   // [NPAIR, DIM, DIM]
    float* __restrict__ out)        // [BATCH, NPAIR, DIM]
{
    extern __shared__ char smem[];
    const int tid   = threadIdx.x;
    const int wid   = tid >> 5;
    const int lid   = tid & 31;
    const int p     = blockIdx.y;
    const int btile = blockIdx.x;

    // decode (i, j) from triu_indices(NF, k=1)
    int i = 0, rem = p;
    while (rem >= NF - 1 - i) { rem -= NF - 1 - i; ++i; }
    const int j = i + 1 + rem;

    // ---- load + split W_p (64x64 fp32 = 1024 float4 chunks, 4/thread) ----
    {
        const float4* src = reinterpret_cast<const float4*>(Wg + (size_t)p * DIM * DIM);
        #pragma unroll
        for (int q = 0; q < 4; ++q) {
            int chunk = tid + 256 * q;
            int row = chunk >> 4, kc = (chunk & 15) * 4;
            uint2 h, l; split_bf16(src[chunk], h, l);
            int off = row * (LDSTR * 2) + kc * 2;
            *reinterpret_cast<uint2*>(smem + SM_WH + off) = h;
            *reinterpret_cast<uint2*>(smem + SM_WL + off) = l;
        }
    }
    // ---- load + split A tile (128x64 fp32 = 2048 float4 chunks, 8/thread) ----
    {
        const float* ab = fe + (((size_t)btile * TILE_M) * NF + i) * DIM;
        #pragma unroll
        for (int q = 0; q < 8; ++q) {
            int chunk = tid + 256 * q;
            int row = chunk >> 4, kc = (chunk & 15) * 4;
            float4 v = *reinterpret_cast<const float4*>(ab + (size_t)row * NF * DIM + kc);
            uint2 h, l; split_bf16(v, h, l);
            int off = row * (LDSTR * 2) + kc * 2;
            *reinterpret_cast<uint2*>(smem + SM_AH + off) = h;
            *reinterpret_cast<uint2*>(smem + SM_AL + off) = l;
        }
    }
    __syncthreads();

    // ---- warp tile: 32 (m) x 32 (n) ----
    const int MR = (wid & 3) * 32;
    const int NC = (wid >> 2) * 32;
    const uint32_t base = s2u(smem);
    const int lr = lid & 15, lc = lid >> 4;

    // ldmatrix addresses (k0 = 0); advance along k by bytes
    uint32_t aAh0 = base + SM_AH + (uint32_t)(MR + lr) * (LDSTR * 2) + lc * 16;
    uint32_t aAh1 = aAh0 + 16 * (LDSTR * 2);
    uint32_t aAl0 = aAh0 + (SM_AL - SM_AH);
    uint32_t aAl1 = aAh1 + (SM_AL - SM_AH);
    uint32_t aWh  = base + SM_WH + (uint32_t)lr * (LDSTR * 2) + NC * 2 + lc * 16;
    uint32_t aWl  = aWh + (SM_WL - SM_WH);

    float acc[2][4][4];
    #pragma unroll
    for (int mi = 0; mi < 2; ++mi)
        #pragma unroll
        for (int ni = 0; ni < 4; ++ni)
            #pragma unroll
            for (int q = 0; q < 4; ++q) acc[mi][ni][q] = 0.f;

    #pragma unroll
    for (int ks = 0; ks < 4; ++ks) {
        const uint32_t kA = (uint32_t)(ks * 32);              // +16 cols in bytes
        const uint32_t kB = (uint32_t)(ks * 16 * (LDSTR * 2)); // +16 rows in bytes

        uint32_t ah[2][4], al[2][4], wh[8], wl[8];
        ldsm_x4(ah[0], aAh0 + kA);
        ldsm_x4(ah[1], aAh1 + kA);
        ldsm_x4(al[0], aAl0 + kA);
        ldsm_x4(al[1], aAl1 + kA);
        ldsm_x4t(wh,     aWh + kB);        // n: NC+0..15  -> {b(n0),b(n8)}
        ldsm_x4t(wh + 4, aWh + kB + 32);   // n: NC+16..31
        ldsm_x4t(wl,     aWl + kB);
        ldsm_x4t(wl + 4, aWl + kB + 32);

        #pragma unroll
        for (int mi = 0; mi < 2; ++mi)
            #pragma unroll
            for (int ni = 0; ni < 4; ++ni) {
                mma_bf16(acc[mi][ni], ah[mi], &wh[ni * 2]);   // Ah*Wh
                mma_bf16(acc[mi][ni], ah[mi], &wl[ni * 2]);   // Ah*Wl
                mma_bf16(acc[mi][ni], al[mi], &wh[ni * 2]);   // Al*Wh
            }
    }

    // ---- epilogue: scale by v_j, store ----
    const int r  = lid >> 2;
    const int cp = (lid & 3) * 2;
    #pragma unroll
    for (int mi = 0; mi < 2; ++mi) {
        #pragma unroll
        for (int h = 0; h < 2; ++h) {
            const int b = btile * TILE_M + MR + mi * 16 + h * 8 + r;
            const float* vjr = fe + ((size_t)b * NF + j) * DIM;
            float* orow = out + ((size_t)b * NPAIR + p) * DIM;
            #pragma unroll
            for (int ni = 0; ni < 4; ++ni) {
                const int col = NC + ni * 8 + cp;
                float2 vj = *reinterpret_cast<const float2*>(vjr + col);
                float2 o;
                o.x = acc[mi][ni][h * 2 + 0] * vj.x;
                o.y = acc[mi][ni][h * 2 + 1] * vj.y;
                *reinterpret_cast<float2*>(orow + col) = o;
            }
        }
    }
}

extern "C" void kernel_launch(void* const* d_in, const int* in_sizes, int n_in,
                              void* d_out, int out_size) {
    const float* fe = (const float*)d_in[0];   // feature_emb [2048, 32, 64] fp32
    const float* W  = (const float*)d_in[1];   // bilinear_W [496, 64, 64] fp32
    float* out = (float*)d_out;                // [2048, 496, 64] fp32

    cudaFuncSetAttribute(bilinear_mma_kernel,
                         cudaFuncAttributeMaxDynamicSharedMemorySize, SM_TOTAL);
    dim3 grid(BATCH / TILE_M, NPAIR);          // (16, 496)
    bilinear_mma_kernel<<<grid, 256, SM_TOTAL>>>(fe, W, out);
}